// round 5
// baseline (speedup 1.0000x reference)
#include <cuda_runtime.h>
#include <cstdint>

#define BATCH 16
#define DIM   256
#define NSEQ  8192
#define QKV_ROWS 384
#define HEADS 4
#define DHEAD 32
#define HID   128

// Scratch (device globals — no runtime allocation allowed)
__device__ float g_qkv[(size_t)BATCH * QKV_ROWS * NSEQ];   // q raw | exp(k) | v
__device__ float g_C[BATCH * HEADS * DHEAD * DHEAD];       // context numerator
__device__ float g_S[BATCH * HEADS * DHEAD];               // softmax denominator
__device__ float g_G[BATCH * DIM * HID];                   // collapsed tail matrix

// ===================== mma.sync bf16 m16n8k16 ==================
#define MMA_BF16(d, a0, a1, a2, a3, b0, b1) \
    asm volatile("mma.sync.aligned.m16n8k16.row.col.f32.bf16.bf16.f32 " \
        "{%0,%1,%2,%3}, {%4,%5,%6,%7}, {%8,%9}, {%0,%1,%2,%3};" \
        : "+f"((d)[0]), "+f"((d)[1]), "+f"((d)[2]), "+f"((d)[3]) \
        : "r"(a0), "r"(a1), "r"(a2), "r"(a3), "r"(b0), "r"(b1))

__device__ __forceinline__ uint32_t pack_bf16(float lo, float hi) {
    uint32_t r;
    asm("cvt.rn.bf16x2.f32 %0, %1, %2;" : "=r"(r) : "f"(hi), "f"(lo));
    return r;
}
__device__ __forceinline__ void bf16_split2(float x, float y, uint32_t& hp, uint32_t& mp) {
    hp = pack_bf16(x, y);
    float fx = __uint_as_float(hp << 16);
    float fy = __uint_as_float(hp & 0xFFFF0000u);
    mp = pack_bf16(x - fx, y - fy);
}

#define KP 40   // halves per row (20 words) -> conflict-free frag LDS

struct SmTiles {
    uint16_t Ah[128 * KP];
    uint16_t Am[128 * KP];
    uint16_t Bh[128 * KP];
    uint16_t Bm[128 * KP];
};
#define DSMEM_BYTES (2 * (int)sizeof(SmTiles))

// ---------- K0: zero accumulators ----------
__global__ void k_zero() {
    int i = blockIdx.x * 256 + threadIdx.x;
    if (i < BATCH * HEADS * DHEAD * DHEAD) g_C[i] = 0.0f;
    if (i < BATCH * HEADS * DHEAD)         g_S[i] = 0.0f;
}

// ================= pipelined GEMM building blocks =================
// prefetch: A 4 float4, B 4 float4 per thread
__device__ __forceinline__ void ldg_A(float4 pa[4], const float* Asrc, int lda, int k0, int tid) {
#pragma unroll
    for (int it = 0; it < 4; it++) {
        const int i  = tid + it * 256;
        const int r  = i >> 3;
        const int c4 = (i & 7) << 2;
        pa[it] = *(const float4*)(Asrc + (size_t)r * lda + k0 + c4);
    }
}
__device__ __forceinline__ void st_A(SmTiles* sm, const float4 pa[4], int tid) {
#pragma unroll
    for (int it = 0; it < 4; it++) {
        const int i  = tid + it * 256;
        const int r  = i >> 3;
        const int c4 = (i & 7) << 2;
        uint32_t h01, m01, h23, m23;
        bf16_split2(pa[it].x, pa[it].y, h01, m01);
        bf16_split2(pa[it].z, pa[it].w, h23, m23);
        *(uint2*)&sm->Ah[r * KP + c4] = make_uint2(h01, h23);
        *(uint2*)&sm->Am[r * KP + c4] = make_uint2(m01, m23);
    }
}
__device__ __forceinline__ void ldg_B(float4 pb[4], const float* Bsrc, int k0, int tid) {
    const int lane = tid & 31;
    const int w    = tid >> 5;
    const int a    = lane >> 3;
    const int p    = (lane >> 2) & 1;
    const int nq   = lane & 3;
    const int n4   = w * 16 + nq * 4;
#pragma unroll
    for (int it = 0; it < 4; it++) {
        const int kloc = it * 8 + 2 * a + p;
        pb[it] = *(const float4*)(Bsrc + (size_t)(k0 + kloc) * NSEQ + n4);
    }
}
__device__ __forceinline__ void st_B(SmTiles* sm, const float4 pb[4], int tid) {
    const int lane = tid & 31;
    const int w    = tid >> 5;
    const int a    = lane >> 3;
    const int p    = (lane >> 2) & 1;
    const int nq   = lane & 3;
    const int n4   = w * 16 + nq * 4;
#pragma unroll
    for (int it = 0; it < 4; it++) {
        float4 t = pb[it];
        float y0 = __shfl_xor_sync(0xFFFFFFFFu, t.x, 4);
        float y1 = __shfl_xor_sync(0xFFFFFFFFu, t.y, 4);
        float y2 = __shfl_xor_sync(0xFFFFFFFFu, t.z, 4);
        float y3 = __shfl_xor_sync(0xFFFFFFFFu, t.w, 4);
        float e0, o0, e1, o1;
        int j0, j1;
        if (p == 0) { j0 = 0; j1 = 1; e0 = t.x; o0 = y0; e1 = t.y; o1 = y1; }
        else        { j0 = 2; j1 = 3; e0 = y2; o0 = t.z; e1 = y3; o1 = t.w; }
        const int cw = it * 4 + a;
        uint32_t h, m;
        bf16_split2(e0, o0, h, m);
        ((uint32_t*)&sm->Bh[(n4 + j0) * KP])[cw] = h;
        ((uint32_t*)&sm->Bm[(n4 + j0) * KP])[cw] = m;
        bf16_split2(e1, o1, h, m);
        ((uint32_t*)&sm->Bh[(n4 + j1) * KP])[cw] = h;
        ((uint32_t*)&sm->Bm[(n4 + j1) * KP])[cw] = m;
    }
}

__device__ __forceinline__ void mma_chunk(const SmTiles* sm, float acc[4][4][4],
                                          int warp_m, int warp_n, int lane) {
    const int lg = lane >> 2;
    const int lc = lane & 3;
    const uint32_t* AhW = (const uint32_t*)sm->Ah;
    const uint32_t* AmW = (const uint32_t*)sm->Am;
    const uint32_t* BhW = (const uint32_t*)sm->Bh;
    const uint32_t* BmW = (const uint32_t*)sm->Bm;
#pragma unroll
    for (int ks = 0; ks < 2; ks++) {
        uint32_t bh[4][2], bm[4][2];
#pragma unroll
        for (int nt = 0; nt < 4; nt++) {
            const int wb = (warp_n * 32 + nt * 8 + lg) * (KP / 2) + ks * 8 + lc;
            bh[nt][0] = BhW[wb]; bh[nt][1] = BhW[wb + 4];
            bm[nt][0] = BmW[wb]; bm[nt][1] = BmW[wb + 4];
        }
#pragma unroll
        for (int mt = 0; mt < 4; mt++) {
            const int wa = (warp_m * 64 + mt * 16 + lg) * (KP / 2) + ks * 8 + lc;
            const uint32_t ah0 = AhW[wa],     ah1 = AhW[wa + 8 * (KP / 2)];
            const uint32_t ah2 = AhW[wa + 4], ah3 = AhW[wa + 8 * (KP / 2) + 4];
            const uint32_t am0 = AmW[wa],     am1 = AmW[wa + 8 * (KP / 2)];
            const uint32_t am2 = AmW[wa + 4], am3 = AmW[wa + 8 * (KP / 2) + 4];
#pragma unroll
            for (int nt = 0; nt < 4; nt++) {
                MMA_BF16(acc[mt][nt], ah0, ah1, ah2, ah3, bh[nt][0], bh[nt][1]);
                MMA_BF16(acc[mt][nt], ah0, ah1, ah2, ah3, bm[nt][0], bm[nt][1]);
                MMA_BF16(acc[mt][nt], am0, am1, am2, am3, bh[nt][0], bh[nt][1]);
            }
        }
    }
}

// ---------- K1: qkv = w_qkv @ x (pipelined) ----------
__global__ __launch_bounds__(256, 1) void k_qkv_mma(const float* __restrict__ x,
                                                    const float* __restrict__ w) {
    extern __shared__ char dsm[];
    SmTiles* stg = (SmTiles*)dsm;
    const int b       = blockIdx.z;
    const int grp     = blockIdx.y;
    const int rowBase = grp * 128;
    const int nBase   = blockIdx.x * 128;
    const int tid     = threadIdx.x;
    const int lane    = tid & 31;
    const int wid     = tid >> 5;
    const int warp_m  = wid & 1;
    const int warp_n  = wid >> 1;

    const float* xb = x + (size_t)b * DIM * NSEQ + nBase;
    const float* wA = w + (size_t)rowBase * DIM;

    float acc[4][4][4];
#pragma unroll
    for (int i = 0; i < 4; i++)
#pragma unroll
        for (int j = 0; j < 4; j++)
#pragma unroll
            for (int c = 0; c < 4; c++) acc[i][j][c] = 0.0f;

    float4 pa[4], pb[4];
    ldg_A(pa, wA, DIM, 0, tid);
    ldg_B(pb, xb, 0, tid);
    st_A(&stg[0], pa, tid);
    st_B(&stg[0], pb, tid);
    __syncthreads();

#pragma unroll
    for (int chunk = 0; chunk < 8; chunk++) {
        const int cur = chunk & 1;
        if (chunk < 7) {
            ldg_A(pa, wA, DIM, (chunk + 1) * 32, tid);
            ldg_B(pb, xb, (chunk + 1) * 32, tid);
        }
        mma_chunk(&stg[cur], acc, warp_m, warp_n, lane);
        if (chunk < 7) {
            st_A(&stg[cur ^ 1], pa, tid);
            st_B(&stg[cur ^ 1], pb, tid);
            __syncthreads();
        }
    }

    const int lg = lane >> 2, lc = lane & 3;
    float* outp = g_qkv + (size_t)b * QKV_ROWS * NSEQ;
#pragma unroll
    for (int mt = 0; mt < 4; mt++) {
        const int row0 = rowBase + warp_m * 64 + mt * 16 + lg;
#pragma unroll
        for (int nt = 0; nt < 4; nt++) {
            const int cn = nBase + warp_n * 32 + nt * 8 + (lc << 1);
            float v0 = acc[mt][nt][0], v1 = acc[mt][nt][1];
            float v2 = acc[mt][nt][2], v3 = acc[mt][nt][3];
            if (grp == 1) { v0 = __expf(v0); v1 = __expf(v1); v2 = __expf(v2); v3 = __expf(v3); }
            *(float2*)(outp + (size_t)row0 * NSEQ + cn)       = make_float2(v0, v1);
            *(float2*)(outp + (size_t)(row0 + 8) * NSEQ + cn) = make_float2(v2, v3);
        }
    }
}

// ---------- K2: C += ek @ v^T ; S += row-sums ----------
__global__ __launch_bounds__(256) void k_ctx() {
    const int b = blockIdx.z, h = blockIdx.y;
    const int nBase = blockIdx.x * 128;
    const int tid = threadIdx.x;

    __shared__ float ek[32][129];
    __shared__ float vv[32][129];

    const float* ekg = g_qkv + ((size_t)(b * QKV_ROWS + 128 + h * DHEAD)) * NSEQ + nBase;
    const float* vg  = g_qkv + ((size_t)(b * QKV_ROWS + 256 + h * DHEAD)) * NSEQ + nBase;

    for (int i = tid; i < 32 * 32; i += 256) {
        int r = i >> 5, c4 = (i & 31) << 2;
        float4 t = *(const float4*)(ekg + (size_t)r * NSEQ + c4);
        ek[r][c4 + 0] = t.x; ek[r][c4 + 1] = t.y; ek[r][c4 + 2] = t.z; ek[r][c4 + 3] = t.w;
        float4 u = *(const float4*)(vg + (size_t)r * NSEQ + c4);
        vv[r][c4 + 0] = u.x; vv[r][c4 + 1] = u.y; vv[r][c4 + 2] = u.z; vv[r][c4 + 3] = u.w;
    }
    __syncthreads();

    const int d  = tid >> 3;
    const int e0 = (tid & 7) << 2;
    float a0 = 0.f, a1 = 0.f, a2 = 0.f, a3 = 0.f, s = 0.f;
#pragma unroll 8
    for (int n = 0; n < 128; n++) {
        float kv = ek[d][n];
        s  += kv;
        a0 += kv * vv[e0 + 0][n];
        a1 += kv * vv[e0 + 1][n];
        a2 += kv * vv[e0 + 2][n];
        a3 += kv * vv[e0 + 3][n];
    }
    float* Cb = g_C + (size_t)(((b * HEADS + h) * DHEAD + d) * DHEAD + e0);
    atomicAdd(Cb + 0, a0); atomicAdd(Cb + 1, a1);
    atomicAdd(Cb + 2, a2); atomicAdd(Cb + 3, a3);
    if (e0 == 0) atomicAdd(g_S + (b * HEADS + h) * DHEAD + d, s);
}

// ---------- K3: G = (w_out-slice @ C) / S ----------
__global__ __launch_bounds__(256) void k_G(const float* __restrict__ w_out) {
    const int h = blockIdx.x, b = blockIdx.y;
    const int o = threadIdx.x;

    __shared__ float Cs[DHEAD * DHEAD];
    __shared__ float Si[DHEAD];

    for (int i = threadIdx.x; i < DHEAD * DHEAD; i += 256)
        Cs[i] = g_C[(size_t)(b * HEADS + h) * DHEAD * DHEAD + i];
    if (threadIdx.x < DHEAD)
        Si[threadIdx.x] = __frcp_rn(g_S[(b * HEADS + h) * DHEAD + threadIdx.x]);
    __syncthreads();

    float wr[DHEAD];
#pragma unroll
    for (int e4 = 0; e4 < DHEAD; e4 += 4) {
        float4 t = *(const float4*)(w_out + (size_t)o * HID + h * DHEAD + e4);
        wr[e4] = t.x; wr[e4 + 1] = t.y; wr[e4 + 2] = t.z; wr[e4 + 3] = t.w;
    }
    float* Gp = g_G + ((size_t)b * DIM + o) * HID + h * DHEAD;
#pragma unroll 4
    for (int d = 0; d < DHEAD; d++) {
        float acc = 0.f;
#pragma unroll
        for (int e = 0; e < DHEAD; e++)
            acc += wr[e] * Cs[d * DHEAD + e];
        Gp[d] = acc * Si[d];
    }
}

// ---------- K4: out = G_b @ q_b + b_out (pipelined) ----------
__global__ __launch_bounds__(256, 1) void k_out_mma(const float* __restrict__ bias,
                                                    float* __restrict__ out) {
    extern __shared__ char dsm[];
    SmTiles* stg = (SmTiles*)dsm;
    const int b       = blockIdx.z;
    const int rowBase = blockIdx.y * 128;
    const int nBase   = blockIdx.x * 128;
    const int tid     = threadIdx.x;
    const int lane    = tid & 31;
    const int wid     = tid >> 5;
    const int warp_m  = wid & 1;
    const int warp_n  = wid >> 1;

    const float* A  = g_G + (size_t)b * DIM * HID + (size_t)rowBase * HID;
    const float* Bq = g_qkv + (size_t)b * QKV_ROWS * NSEQ + nBase;

    float acc[4][4][4];
#pragma unroll
    for (int i = 0; i < 4; i++)
#pragma unroll
        for (int j = 0; j < 4; j++)
#pragma unroll
            for (int c = 0; c < 4; c++) acc[i][j][c] = 0.0f;

    float4 pa[4], pb[4];
    ldg_A(pa, A, HID, 0, tid);
    ldg_B(pb, Bq, 0, tid);
    st_A(&stg[0], pa, tid);
    st_B(&stg[0], pb, tid);
    __syncthreads();

#pragma unroll
    for (int chunk = 0; chunk < 4; chunk++) {
        const int cur = chunk & 1;
        if (chunk < 3) {
            ldg_A(pa, A, HID, (chunk + 1) * 32, tid);
            ldg_B(pb, Bq, (chunk + 1) * 32, tid);
        }
        mma_chunk(&stg[cur], acc, warp_m, warp_n, lane);
        if (chunk < 3) {
            st_A(&stg[cur ^ 1], pa, tid);
            st_B(&stg[cur ^ 1], pb, tid);
            __syncthreads();
        }
    }

    const int lg = lane >> 2, lc = lane & 3;
    float* outb = out + (size_t)b * DIM * NSEQ;
#pragma unroll
    for (int mt = 0; mt < 4; mt++) {
        const int row0 = rowBase + warp_m * 64 + mt * 16 + lg;
        const float bi0 = bias[row0], bi1 = bias[row0 + 8];
#pragma unroll
        for (int nt = 0; nt < 4; nt++) {
            const int cn = nBase + warp_n * 32 + nt * 8 + (lc << 1);
            *(float2*)(outb + (size_t)row0 * NSEQ + cn) =
                make_float2(acc[mt][nt][0] + bi0, acc[mt][nt][1] + bi0);
            *(float2*)(outb + (size_t)(row0 + 8) * NSEQ + cn) =
                make_float2(acc[mt][nt][2] + bi1, acc[mt][nt][3] + bi1);
        }
    }
}

extern "C" void kernel_launch(void* const* d_in, const int* in_sizes, int n_in,
                              void* d_out, int out_size) {
    const float* x     = (const float*)d_in[0];
    const float* w_qkv = (const float*)d_in[1];
    const float* w_out = (const float*)d_in[2];
    const float* b_out = (const float*)d_in[3];
    float* out = (float*)d_out;

    cudaFuncSetAttribute(k_qkv_mma, cudaFuncAttributeMaxDynamicSharedMemorySize, DSMEM_BYTES);
    cudaFuncSetAttribute(k_out_mma, cudaFuncAttributeMaxDynamicSharedMemorySize, DSMEM_BYTES);

    k_zero<<<257, 256>>>();
    k_qkv_mma<<<dim3(NSEQ / 128, 3, BATCH), 256, DSMEM_BYTES>>>(x, w_qkv);
    k_ctx<<<dim3(NSEQ / 128, HEADS, BATCH), 256>>>();
    k_G<<<dim3(HEADS, BATCH), 256>>>(w_out);
    k_out_mma<<<dim3(NSEQ / 128, 2, BATCH), 256, DSMEM_BYTES>>>(b_out, out);
}

// round 7
// speedup vs baseline: 1.2491x; 1.2491x over previous
#include <cuda_runtime.h>
#include <cstdint>

#define BATCH 16
#define DIM   256
#define NSEQ  8192
#define QKV_ROWS 384
#define HEADS 4
#define DHEAD 32
#define HID   128

// Scratch (device globals — no runtime allocation allowed)
__device__ float g_qkv[(size_t)BATCH * QKV_ROWS * NSEQ];   // q raw | exp(k) | v
__device__ float g_C[BATCH * HEADS * DHEAD * DHEAD];       // context numerator
__device__ float g_S[BATCH * HEADS * DHEAD];               // softmax denominator
__device__ float g_G[BATCH * DIM * HID];                   // collapsed tail matrix

// ===================== mma.sync bf16 m16n8k16 ==================
#define MMA_BF16(d, a0, a1, a2, a3, b0, b1) \
    asm volatile("mma.sync.aligned.m16n8k16.row.col.f32.bf16.bf16.f32 " \
        "{%0,%1,%2,%3}, {%4,%5,%6,%7}, {%8,%9}, {%0,%1,%2,%3};" \
        : "+f"((d)[0]), "+f"((d)[1]), "+f"((d)[2]), "+f"((d)[3]) \
        : "r"(a0), "r"(a1), "r"(a2), "r"(a3), "r"(b0), "r"(b1))

#define LDSM_X4(r0, r1, r2, r3, addr) \
    asm volatile("ldmatrix.sync.aligned.m8n8.x4.shared.b16 {%0,%1,%2,%3}, [%4];" \
        : "=r"(r0), "=r"(r1), "=r"(r2), "=r"(r3) : "r"(addr))

#define LDSM_X4_T(r0, r1, r2, r3, addr) \
    asm volatile("ldmatrix.sync.aligned.m8n8.x4.trans.shared.b16 {%0,%1,%2,%3}, [%4];" \
        : "=r"(r0), "=r"(r1), "=r"(r2), "=r"(r3) : "r"(addr))

__device__ __forceinline__ uint32_t smem_u32(const void* p) {
    uint32_t a;
    asm("{ .reg .u64 t; cvta.to.shared.u64 t, %1; cvt.u32.u64 %0, t; }" : "=r"(a) : "l"(p));
    return a;
}

__device__ __forceinline__ uint32_t pack_bf16(float lo, float hi) {
    uint32_t r;
    asm("cvt.rn.bf16x2.f32 %0, %1, %2;" : "=r"(r) : "f"(hi), "f"(lo));
    return r;
}
__device__ __forceinline__ void bf16_split2(float x, float y, uint32_t& hp, uint32_t& mp) {
    hp = pack_bf16(x, y);
    float fx = __uint_as_float(hp << 16);
    float fy = __uint_as_float(hp & 0xFFFF0000u);
    mp = pack_bf16(x - fx, y - fy);
}

// A tile: [m 128][k 40 halves]  stride 80B  (conflict-free LDSM)
// B tile: [k 32][n 136 halves]  stride 272B (conflict-free LDSM)
#define AKP 40
#define BNP 136

struct SmTiles {
    uint16_t Ah[128 * AKP];
    uint16_t Am[128 * AKP];
    uint16_t Bh[32 * BNP];
    uint16_t Bm[32 * BNP];
};

// ---------- K0: zero accumulators (MUST cover all 65536 C entries every replay) ----------
__global__ void k_zero() {
    int i = blockIdx.x * 256 + threadIdx.x;
    if (i < BATCH * HEADS * DHEAD * DHEAD) g_C[i] = 0.0f;
    if (i < BATCH * HEADS * DHEAD)         g_S[i] = 0.0f;
}

// ================= GEMM building blocks =================
__device__ __forceinline__ void load_A_chunk(SmTiles* sm, const float* Asrc, int lda,
                                             int k0, int tid) {
#pragma unroll
    for (int it = 0; it < 4; it++) {
        const int i  = tid + it * 256;
        const int r  = i >> 3;
        const int c4 = (i & 7) << 2;
        float4 t = *(const float4*)(Asrc + (size_t)r * lda + k0 + c4);
        uint32_t h01, m01, h23, m23;
        bf16_split2(t.x, t.y, h01, m01);
        bf16_split2(t.z, t.w, h23, m23);
        *(uint2*)&sm->Ah[r * AKP + c4] = make_uint2(h01, h23);
        *(uint2*)&sm->Am[r * AKP + c4] = make_uint2(m01, m23);
    }
}

// B natural orientation: k rows, n columns.
__device__ __forceinline__ void load_B_chunk(SmTiles* sm, const float* Bsrc,
                                             int k0, int tid) {
    const int kb = tid >> 5;
    const int n4 = (tid & 31) << 2;
#pragma unroll
    for (int it = 0; it < 4; it++) {
        const int k = kb + it * 8;
        float4 t = *(const float4*)(Bsrc + (size_t)(k0 + k) * NSEQ + n4);
        uint32_t h01, m01, h23, m23;
        bf16_split2(t.x, t.y, h01, m01);
        bf16_split2(t.z, t.w, h23, m23);
        *(uint2*)&sm->Bh[k * BNP + n4] = make_uint2(h01, h23);
        *(uint2*)&sm->Bm[k * BNP + n4] = make_uint2(m01, m23);
    }
}

__device__ __forceinline__ void mma_chunk(const SmTiles* sm, float acc[4][4][4],
                                          int warp_m, int warp_n, int lane) {
    const int lr8 = lane & 15;
    const int lh  = lane >> 4;
    const uint32_t aBaseH = smem_u32(sm->Ah);
    const uint32_t aBaseM = smem_u32(sm->Am);
    const uint32_t bBaseH = smem_u32(sm->Bh);
    const uint32_t bBaseM = smem_u32(sm->Bm);

#pragma unroll
    for (int ks = 0; ks < 2; ks++) {
        uint32_t bh[4][2], bm[4][2];
#pragma unroll
        for (int np = 0; np < 2; np++) {
            const int n0 = warp_n * 32 + np * 16;
            const uint32_t baddr = (uint32_t)((ks * 16 + lr8) * (BNP * 2) + n0 * 2 + lh * 16);
            LDSM_X4_T(bh[np * 2][0], bh[np * 2][1], bh[np * 2 + 1][0], bh[np * 2 + 1][1],
                      bBaseH + baddr);
            LDSM_X4_T(bm[np * 2][0], bm[np * 2][1], bm[np * 2 + 1][0], bm[np * 2 + 1][1],
                      bBaseM + baddr);
        }
#pragma unroll
        for (int mt = 0; mt < 4; mt++) {
            const int m0 = warp_m * 64 + mt * 16;
            const uint32_t aaddr = (uint32_t)((m0 + lr8) * (AKP * 2) + ks * 32 + lh * 16);
            uint32_t ah0, ah1, ah2, ah3, am0, am1, am2, am3;
            LDSM_X4(ah0, ah1, ah2, ah3, aBaseH + aaddr);
            LDSM_X4(am0, am1, am2, am3, aBaseM + aaddr);
#pragma unroll
            for (int nt = 0; nt < 4; nt++) {
                MMA_BF16(acc[mt][nt], ah0, ah1, ah2, ah3, bh[nt][0], bh[nt][1]);
                MMA_BF16(acc[mt][nt], ah0, ah1, ah2, ah3, bm[nt][0], bm[nt][1]);
                MMA_BF16(acc[mt][nt], am0, am1, am2, am3, bh[nt][0], bh[nt][1]);
            }
        }
    }
}

// ---------- K1: qkv = w_qkv @ x ----------
__global__ __launch_bounds__(256, 2) void k_qkv_mma(const float* __restrict__ x,
                                                    const float* __restrict__ w) {
    __shared__ SmTiles sm;
    const int b       = blockIdx.z;
    const int grp     = blockIdx.y;
    const int rowBase = grp * 128;
    const int nBase   = blockIdx.x * 128;
    const int tid     = threadIdx.x;
    const int lane    = tid & 31;
    const int wid     = tid >> 5;
    const int warp_m  = wid & 1;
    const int warp_n  = wid >> 1;

    const float* xb = x + (size_t)b * DIM * NSEQ + nBase;
    const float* wA = w + (size_t)rowBase * DIM;

    float acc[4][4][4];
#pragma unroll
    for (int i = 0; i < 4; i++)
#pragma unroll
        for (int j = 0; j < 4; j++)
#pragma unroll
            for (int c = 0; c < 4; c++) acc[i][j][c] = 0.0f;

    for (int chunk = 0; chunk < 8; chunk++) {
        const int k0 = chunk * 32;
        load_A_chunk(&sm, wA, DIM, k0, tid);
        load_B_chunk(&sm, xb, k0, tid);
        __syncthreads();
        mma_chunk(&sm, acc, warp_m, warp_n, lane);
        __syncthreads();
    }

    const int lg = lane >> 2, lc = lane & 3;
    float* outp = g_qkv + (size_t)b * QKV_ROWS * NSEQ;
#pragma unroll
    for (int mt = 0; mt < 4; mt++) {
        const int row0 = rowBase + warp_m * 64 + mt * 16 + lg;
#pragma unroll
        for (int nt = 0; nt < 4; nt++) {
            const int cn = nBase + warp_n * 32 + nt * 8 + (lc << 1);
            float v0 = acc[mt][nt][0], v1 = acc[mt][nt][1];
            float v2 = acc[mt][nt][2], v3 = acc[mt][nt][3];
            if (grp == 1) { v0 = __expf(v0); v1 = __expf(v1); v2 = __expf(v2); v3 = __expf(v3); }
            *(float2*)(outp + (size_t)row0 * NSEQ + cn)       = make_float2(v0, v1);
            *(float2*)(outp + (size_t)(row0 + 8) * NSEQ + cn) = make_float2(v2, v3);
        }
    }
}

// ---------- K2: C += ek @ v^T ; S += row-sums ----------
__global__ __launch_bounds__(256) void k_ctx() {
    const int b = blockIdx.z, h = blockIdx.y;
    const int nBase = blockIdx.x * 128;
    const int tid = threadIdx.x;

    __shared__ float ek[32][129];
    __shared__ float vv[32][129];

    const float* ekg = g_qkv + ((size_t)(b * QKV_ROWS + 128 + h * DHEAD)) * NSEQ + nBase;
    const float* vg  = g_qkv + ((size_t)(b * QKV_ROWS + 256 + h * DHEAD)) * NSEQ + nBase;

    for (int i = tid; i < 32 * 32; i += 256) {
        int r = i >> 5, c4 = (i & 31) << 2;
        float4 t = *(const float4*)(ekg + (size_t)r * NSEQ + c4);
        ek[r][c4 + 0] = t.x; ek[r][c4 + 1] = t.y; ek[r][c4 + 2] = t.z; ek[r][c4 + 3] = t.w;
        float4 u = *(const float4*)(vg + (size_t)r * NSEQ + c4);
        vv[r][c4 + 0] = u.x; vv[r][c4 + 1] = u.y; vv[r][c4 + 2] = u.z; vv[r][c4 + 3] = u.w;
    }
    __syncthreads();

    const int d  = tid >> 3;
    const int e0 = (tid & 7) << 2;
    float a0 = 0.f, a1 = 0.f, a2 = 0.f, a3 = 0.f, s = 0.f;
#pragma unroll 8
    for (int n = 0; n < 128; n++) {
        float kv = ek[d][n];
        s  += kv;
        a0 += kv * vv[e0 + 0][n];
        a1 += kv * vv[e0 + 1][n];
        a2 += kv * vv[e0 + 2][n];
        a3 += kv * vv[e0 + 3][n];
    }
    float* Cb = g_C + (size_t)(((b * HEADS + h) * DHEAD + d) * DHEAD + e0);
    atomicAdd(Cb + 0, a0); atomicAdd(Cb + 1, a1);
    atomicAdd(Cb + 2, a2); atomicAdd(Cb + 3, a3);
    if (e0 == 0) atomicAdd(g_S + (b * HEADS + h) * DHEAD + d, s);
}

// ---------- K3: G = (w_out-slice @ C) / S ----------
__global__ __launch_bounds__(256) void k_G(const float* __restrict__ w_out) {
    const int h = blockIdx.x, b = blockIdx.y;
    const int o = threadIdx.x;

    __shared__ float Cs[DHEAD * DHEAD];
    __shared__ float Si[DHEAD];

    for (int i = threadIdx.x; i < DHEAD * DHEAD; i += 256)
        Cs[i] = g_C[(size_t)(b * HEADS + h) * DHEAD * DHEAD + i];
    if (threadIdx.x < DHEAD)
        Si[threadIdx.x] = __frcp_rn(g_S[(b * HEADS + h) * DHEAD + threadIdx.x]);
    __syncthreads();

    float wr[DHEAD];
#pragma unroll
    for (int e4 = 0; e4 < DHEAD; e4 += 4) {
        float4 t = *(const float4*)(w_out + (size_t)o * HID + h * DHEAD + e4);
        wr[e4] = t.x; wr[e4 + 1] = t.y; wr[e4 + 2] = t.z; wr[e4 + 3] = t.w;
    }
    float* Gp = g_G + ((size_t)b * DIM + o) * HID + h * DHEAD;
#pragma unroll 4
    for (int d = 0; d < DHEAD; d++) {
        float acc = 0.f;
#pragma unroll
        for (int e = 0; e < DHEAD; e++)
            acc += wr[e] * Cs[d * DHEAD + e];
        Gp[d] = acc * Si[d];
    }
}

// ---------- K4: out = G_b @ q_b + b_out ----------
__global__ __launch_bounds__(256, 2) void k_out_mma(const float* __restrict__ bias,
                                                    float* __restrict__ out) {
    __shared__ SmTiles sm;
    const int b       = blockIdx.z;
    const int rowBase = blockIdx.y * 128;
    const int nBase   = blockIdx.x * 128;
    const int tid     = threadIdx.x;
    const int lane    = tid & 31;
    const int wid     = tid >> 5;
    const int warp_m  = wid & 1;
    const int warp_n  = wid >> 1;

    const float* A  = g_G + (size_t)b * DIM * HID + (size_t)rowBase * HID;
    const float* Bq = g_qkv + (size_t)b * QKV_ROWS * NSEQ + nBase;

    float acc[4][4][4];
#pragma unroll
    for (int i = 0; i < 4; i++)
#pragma unroll
        for (int j = 0; j < 4; j++)
#pragma unroll
            for (int c = 0; c < 4; c++) acc[i][j][c] = 0.0f;

    for (int chunk = 0; chunk < 4; chunk++) {
        const int k0 = chunk * 32;
        load_A_chunk(&sm, A, HID, k0, tid);
        load_B_chunk(&sm, Bq, k0, tid);
        __syncthreads();
        mma_chunk(&sm, acc, warp_m, warp_n, lane);
        __syncthreads();
    }

    const int lg = lane >> 2, lc = lane & 3;
    float* outb = out + (size_t)b * DIM * NSEQ;
#pragma unroll
    for (int mt = 0; mt < 4; mt++) {
        const int row0 = rowBase + warp_m * 64 + mt * 16 + lg;
        const float bi0 = bias[row0], bi1 = bias[row0 + 8];
#pragma unroll
        for (int nt = 0; nt < 4; nt++) {
            const int cn = nBase + warp_n * 32 + nt * 8 + (lc << 1);
            *(float2*)(outb + (size_t)row0 * NSEQ + cn) =
                make_float2(acc[mt][nt][0] + bi0, acc[mt][nt][1] + bi0);
            *(float2*)(outb + (size_t)(row0 + 8) * NSEQ + cn) =
                make_float2(acc[mt][nt][2] + bi1, acc[mt][nt][3] + bi1);
        }
    }
}

extern "C" void kernel_launch(void* const* d_in, const int* in_sizes, int n_in,
                              void* d_out, int out_size) {
    const float* x     = (const float*)d_in[0];
    const float* w_qkv = (const float*)d_in[1];
    const float* w_out = (const float*)d_in[2];
    const float* b_out = (const float*)d_in[3];
    float* out = (float*)d_out;

    k_zero<<<257, 256>>>();   // covers all 65536 g_C + 2048 g_S entries
    k_qkv_mma<<<dim3(NSEQ / 128, 3, BATCH), 256>>>(x, w_qkv);
    k_ctx<<<dim3(NSEQ / 128, HEADS, BATCH), 256>>>();
    k_G<<<dim3(HEADS, BATCH), 256>>>(w_out);
    k_out_mma<<<dim3(NSEQ / 128, 2, BATCH), 256>>>(b_out, out);
}